// round 13
// baseline (speedup 1.0000x reference)
#include <cuda_runtime.h>
#include <cuda_fp16.h>
#include <cstdint>

// Problem constants
#define B_   128
#define T_   1024
#define H_   512
#define G_   2048
#define V_   256
#define NBLK 128      // 32 gate-groups (16 units) x 4 batch-groups (32 rows)
#define NTHR 512      // 16 warps = 4 gate-type warps x 4 k-splits

// SMEM map (bytes)
//  WF: A-fragments of W slice, [pass(2)][mt(4)][kstep(32)] x 512B = 131072
//  HF: B-fragments of h tile,  [pass(2)][nt(4)][kstep(32)] x 256B =  65536
//  GS: 4 k-split partial gate buffers [64 g][33 b] f32            =  33792
#define SM_WF  0
#define SM_HF  131072
#define SM_GS  196608
#define SM_XLS 230400
#define SMEM_BYTES 230528

// Device-global scratch (allocation-free per harness rules)
__device__ float    g_WihT[V_*G_];        // projT[v][g] with biases folded
__device__ float    g_h[2][B_*H_];        // double-buffered h, [b][k] fp32
__device__ unsigned g_bar;

__device__ __forceinline__ float sigf(float x) { return 1.0f / (1.0f + expf(-x)); }

__device__ __forceinline__ void mma16816(float d[4], const uint4& a, const uint2& b) {
    asm volatile(
        "mma.sync.aligned.m16n8k16.row.col.f32.f16.f16.f32 "
        "{%0,%1,%2,%3}, {%4,%5,%6,%7}, {%8,%9}, {%0,%1,%2,%3};"
        : "+f"(d[0]), "+f"(d[1]), "+f"(d[2]), "+f"(d[3])
        : "r"(a.x), "r"(a.y), "r"(a.z), "r"(a.w), "r"(b.x), "r"(b.y));
}

__device__ __forceinline__ uint32_t h2u(__half2 h) { return *(uint32_t*)&h; }

// fp32 pair -> (hi fp16x2, lo fp16x2) with lo = x - float(hi)
__device__ __forceinline__ void split2(float2 v, uint32_t& hi, uint32_t& lo) {
    __half2 h = __floats2half2_rn(v.x, v.y);
    float2 f = __half22float2(h);
    __half2 l = __floats2half2_rn(v.x - f.x, v.y - f.y);
    hi = h2u(h); lo = h2u(l);
}

// Per-launch init: reset barrier, zero h0, build projection table
// projT[v][g] = W_ih[g][v] + b_ih[g] + b_hh[g]
__global__ void init_kernel(const float* __restrict__ W_ih,
                            const float* __restrict__ b_ih,
                            const float* __restrict__ b_hh) {
    int idx = blockIdx.x * blockDim.x + threadIdx.x;
    int stride = gridDim.x * blockDim.x;
    if (idx == 0) g_bar = 0u;
    for (int i = idx; i < V_*G_; i += stride) {
        int v = i >> 11;
        int g = i & (G_ - 1);
        g_WihT[i] = W_ih[g*V_ + v] + b_ih[g] + b_hh[g];
    }
    for (int i = idx; i < B_*H_; i += stride) g_h[0][i] = 0.f;
}

extern __shared__ char smem_raw[];

__global__ __launch_bounds__(NTHR, 1)
void lstm_persistent(const int* __restrict__ x, const int* __restrict__ x_len,
                     const float* __restrict__ W_hh, float* __restrict__ out) {
    char*  sm  = smem_raw;
    float* Gs  = (float*)(sm + SM_GS);
    int*   xls = (int*)(sm + SM_XLS);

    const int tid  = threadIdx.x;
    const int lane = tid & 31;
    const int warp = tid >> 5;
    const int gg   = blockIdx.x & 31;   // gate group (16 h-units, 64 gate rows)
    const int bg   = blockIdx.x >> 5;   // batch group (32 rows)
    const int hu0  = gg * 16;
    const int b0   = bg * 32;

    // ---- Prologue: pack W slice into A-fragment layout (hi/lo fp16) ----
    // A m16n8k16 fragment: lane l holds a0=(r,c..c+1) a1=(r+8,c..) a2=(r,c+8..) a3=(r+8,c+8..)
    // with r=l>>2, c=2*(l&3). Block(pass,mt,s) = 512B, lane chunk = 16B.
    {
        const int combo = tid >> 2;        // (mt, s)  0..127
        const int q     = tid & 3;
        const int mt = combo >> 5;         // gate type 0..3 (16 rows each)
        const int s  = combo & 31;         // k-step
        char* wfhi = sm + SM_WF + (size_t)((0*4 + mt)*32 + s)*512;
        char* wflo = sm + SM_WF + (size_t)((1*4 + mt)*32 + s)*512;
        for (int l2 = q*8; l2 < q*8 + 8; ++l2) {
            const int r = l2 >> 2, c = 2*(l2 & 3);
            const float* w0 = W_hh + (size_t)(mt*512 + hu0 + r)*H_ + s*16 + c;
            const float* w1 = w0 + 8*H_;
            float2 w00 = *(const float2*)w0;
            float2 w02 = *(const float2*)(w0 + 8);
            float2 w10 = *(const float2*)w1;
            float2 w12 = *(const float2*)(w1 + 8);
            uint4 hi, lo;
            split2(w00, hi.x, lo.x);
            split2(w10, hi.y, lo.y);
            split2(w02, hi.z, lo.z);
            split2(w12, hi.w, lo.w);
            *(uint4*)(wfhi + l2*16) = hi;
            *(uint4*)(wflo + l2*16) = lo;
        }
    }
    if (tid < 32) xls[tid] = x_len[b0 + tid];
    __syncthreads();

    // GEMM roles: warp = (mt in 0..3: gate type m16 tile, kh in 0..3: k quarter)
    const int mt = warp & 3;
    const int kh = warp >> 2;

    // Pointwise roles: b = tid>>4 (32 rows), u = tid&15 (1 unit) -> coalesced gmem
    const int pu = tid & 15;
    const int pb = tid >> 4;
    float creg = 0.f;

    // Convert roles: thread = (cb batch row, jb4 k-phase, iq k-step quarter)
    const int cb  = tid >> 4;             // 0..31
    const int jb4 = tid & 3;              // 0..3
    const int iq  = (tid >> 2) & 3;       // 0..3
    const int cnt = cb >> 3;              // B n-tile
    const int cl2 = (cb & 7)*4 + jb4;     // fragment lane

    for (int t = 0; t < T_; ++t) {
        const int cur = t & 1, nxt = cur ^ 1;

        // ---- Convert h -> fp16 hi/lo B-fragment tiles ----
        // B k16n8 fragment: lane l holds b0 = rows 2*(l&3)+{0,1}, b1 = rows +8, col l>>2.
        {
            const float* hrow = g_h[cur] + (size_t)(b0 + cb)*H_;
            char* hfhi = sm + SM_HF + (size_t)(cnt*32)*256;
            char* hflo = hfhi + 4*32*256;
            #pragma unroll
            for (int i = iq*8; i < iq*8 + 8; ++i) {
                float2 v0 = *(const float2*)(hrow + 2*jb4 + 16*i);      // b0 halves
                float2 v1 = *(const float2*)(hrow + 2*jb4 + 16*i + 8);  // b1 halves
                uint2 hiw, low;
                split2(v0, hiw.x, low.x);
                split2(v1, hiw.y, low.y);
                const int off = i*256 + cl2*8;
                *(uint2*)(hfhi + off) = hiw;
                *(uint2*)(hflo + off) = low;
            }
        }
        __syncthreads();

        // ---- GEMM: 3-pass fp16 split, warp tile 16g x 32b over K/4 ----
        float d[4][4];
        #pragma unroll
        for (int b = 0; b < 4; ++b)
            #pragma unroll
            for (int c = 0; c < 4; ++c) d[b][c] = 0.f;

        #pragma unroll
        for (int pass = 0; pass < 3; ++pass) {
            const int pa  = (pass == 2) ? 1 : 0;   // A: hi,hi,lo
            const int pbp = (pass == 1) ? 1 : 0;   // B: hi,lo,hi
            const char* Ab = sm + SM_WF + (size_t)(pa*4 + mt)*(32*512);
            const char* Bb = sm + SM_HF + (size_t)(pbp*4)*(32*256);
            #pragma unroll 4
            for (int s8 = 0; s8 < 8; ++s8) {
                const int s = kh*8 + s8;
                uint4 A0 = *(const uint4*)(Ab + s*512 + lane*16);
                uint2 Bv[4];
                #pragma unroll
                for (int nt = 0; nt < 4; ++nt)
                    Bv[nt] = *(const uint2*)(Bb + nt*(32*256) + s*256 + lane*8);
                #pragma unroll
                for (int nt = 0; nt < 4; ++nt)
                    mma16816(d[nt], A0, Bv[nt]);
            }
        }

        // ---- Stage k-split partials to Gs[kh] ----
        // D m16n8: lane holds d0=(r,c) d1=(r,c+1) d2=(r+8,c) d3=(r+8,c+1)
        {
            float* gsb = Gs + kh*2112;
            const int rr = lane >> 2, cc = 2*(lane & 3);
            const int g0 = mt*16 + rr;
            #pragma unroll
            for (int nt = 0; nt < 4; ++nt) {
                const int col = nt*8 + cc;
                gsb[g0*33 + col]         = d[nt][0];
                gsb[g0*33 + col + 1]     = d[nt][1];
                gsb[(g0+8)*33 + col]     = d[nt][2];
                gsb[(g0+8)*33 + col + 1] = d[nt][3];
            }
        }
        __syncthreads();

        // ---- Pointwise LSTM cell (1 h-unit per thread, c in register) ----
        {
            const int b = pb, u = pu;
            float gv[4];
            #pragma unroll
            for (int gt = 0; gt < 4; ++gt) {
                const int g = gt*16 + u;
                gv[gt] = Gs[g*33 + b] + Gs[2112 + g*33 + b]
                       + Gs[2*2112 + g*33 + b] + Gs[3*2112 + g*33 + b];
            }
            const int vb = x[(size_t)(b0 + b)*T_ + t];
            const float* pj = g_WihT + (size_t)vb*G_ + hu0 + u;
            const float hprev = g_h[cur][(size_t)(b0+b)*H_ + hu0 + u];

            const float iv = sigf(gv[0] + pj[0]);
            const float fv = sigf(gv[1] + pj[512]);
            const float gvv = tanhf(gv[2] + pj[1024]);
            const float ov = sigf(gv[3] + pj[1536]);
            const float cn = fv*creg + iv*gvv;
            const float hn = ov*tanhf(cn);

            const bool m = (t < xls[b]);
            const float hc = m ? hn : hprev;
            if (m) creg = cn;

            g_h[nxt][(size_t)(b0+b)*H_ + hu0 + u] = hc;                 // coalesced 64B runs
            out[((size_t)(b0+b)*T_ + t)*H_ + hu0 + u] = m ? hn : 0.f;   // coalesced 64B runs

            if (t == T_ - 1) {
                const size_t hoff = (size_t)B_*T_*H_ + (size_t)(b0+b)*H_ + hu0 + u;
                out[hoff] = hc;
                out[hoff + (size_t)B_*H_] = creg;
            }
        }

        // ---- Grid barrier (128 CTAs, 1/SM, co-resident) ----
        if (t + 1 < T_) {
            __threadfence();          // release all this block's stores
            __syncthreads();
            if (tid == 0) {
                atomicAdd(&g_bar, 1u);
                const unsigned target = (unsigned)NBLK * (unsigned)(t + 1);
                while (*((volatile unsigned*)&g_bar) < target) { }
                __threadfence();      // acquire
            }
            __syncthreads();
        }
    }
}

extern "C" void kernel_launch(void* const* d_in, const int* in_sizes, int n_in,
                              void* d_out, int out_size) {
    const int*   x     = (const int*)d_in[0];
    const int*   x_len = (const int*)d_in[1];
    const float* W_ih  = (const float*)d_in[2];
    const float* W_hh  = (const float*)d_in[3];
    const float* b_ih  = (const float*)d_in[4];
    const float* b_hh  = (const float*)d_in[5];
    float* out = (float*)d_out;

    cudaFuncSetAttribute(lstm_persistent,
                         cudaFuncAttributeMaxDynamicSharedMemorySize, SMEM_BYTES);

    init_kernel<<<256, 256>>>(W_ih, b_ih, b_hh);
    lstm_persistent<<<NBLK, NTHR, SMEM_BYTES>>>(x, x_len, W_hh, out);
}

// round 14
// speedup vs baseline: 1.1680x; 1.1680x over previous
#include <cuda_runtime.h>
#include <cuda_fp16.h>
#include <cstdint>

// Problem constants
#define B_   128
#define T_   1024
#define H_   512
#define G_   2048
#define V_   256
#define NBLK 128      // 32 gate-groups (16 units) x 4 batch-groups (32 rows)
#define NTHR 512      // 16 warps = 4 gate-type warps x 4 k-splits

// SMEM map (bytes)
//  WF: A-fragments of W slice, [pass(2)][mt(4)][kstep(32)] x 512B = 131072
//  HF: B-fragments of h tile,  [pass(2)][nt(4)][kstep(32)] x 256B =  65536
//  GS: 4 k-split partial gate buffers [64 g][33 b] f32            =  33792
#define SM_WF  0
#define SM_HF  131072
#define SM_GS  196608
#define SMEM_BYTES 230528

// Device-global scratch (allocation-free per harness rules)
__device__ float    g_WihT[V_*G_];        // projT[v][g] with biases folded
__device__ float    g_h[2][B_*H_];        // double-buffered h, [b][k] fp32
__device__ unsigned g_bar;

__device__ __forceinline__ float sigf(float x) { return 1.0f / (1.0f + expf(-x)); }

__device__ __forceinline__ void mma16816(float d[4], const uint4& a, const uint2& b) {
    asm volatile(
        "mma.sync.aligned.m16n8k16.row.col.f32.f16.f16.f32 "
        "{%0,%1,%2,%3}, {%4,%5,%6,%7}, {%8,%9}, {%0,%1,%2,%3};"
        : "+f"(d[0]), "+f"(d[1]), "+f"(d[2]), "+f"(d[3])
        : "r"(a.x), "r"(a.y), "r"(a.z), "r"(a.w), "r"(b.x), "r"(b.y));
}

__device__ __forceinline__ uint32_t h2u(__half2 h) { return *(uint32_t*)&h; }

// fp32 pair -> (hi fp16x2, lo fp16x2) with lo = x - float(hi)
__device__ __forceinline__ void split2(float2 v, uint32_t& hi, uint32_t& lo) {
    __half2 h = __floats2half2_rn(v.x, v.y);
    float2 f = __half22float2(h);
    __half2 l = __floats2half2_rn(v.x - f.x, v.y - f.y);
    hi = h2u(h); lo = h2u(l);
}

// Per-launch init: reset barrier, zero h0, build projection table
// projT[v][g] = W_ih[g][v] + b_ih[g] + b_hh[g]
__global__ void init_kernel(const float* __restrict__ W_ih,
                            const float* __restrict__ b_ih,
                            const float* __restrict__ b_hh) {
    int idx = blockIdx.x * blockDim.x + threadIdx.x;
    int stride = gridDim.x * blockDim.x;
    if (idx == 0) g_bar = 0u;
    for (int i = idx; i < V_*G_; i += stride) {
        int v = i >> 11;
        int g = i & (G_ - 1);
        g_WihT[i] = W_ih[g*V_ + v] + b_ih[g] + b_hh[g];
    }
    for (int i = idx; i < B_*H_; i += stride) g_h[0][i] = 0.f;
}

extern __shared__ char smem_raw[];

__global__ __launch_bounds__(NTHR, 1)
void lstm_persistent(const int* __restrict__ x, const int* __restrict__ x_len,
                     const float* __restrict__ W_hh, float* __restrict__ out) {
    char*  sm = smem_raw;
    float* Gs = (float*)(sm + SM_GS);

    const int tid  = threadIdx.x;
    const int lane = tid & 31;
    const int warp = tid >> 5;
    const int gg   = blockIdx.x & 31;   // gate group (16 h-units, 64 gate rows)
    const int bg   = blockIdx.x >> 5;   // batch group (32 rows)
    const int hu0  = gg * 16;
    const int b0   = bg * 32;

    // ---- Prologue: pack W slice into A-fragment layout (hi/lo fp16) ----
    // A m16n8k16 fragment: lane l holds a0=(r,c..c+1) a1=(r+8,c..) a2=(r,c+8..) a3=(r+8,c+8..)
    // with r=l>>2, c=2*(l&3). Block(pass,mt,s) = 512B, lane chunk = 16B.
    {
        const int combo = tid >> 2;        // (mt, s)  0..127
        const int q     = tid & 3;
        const int mt = combo >> 5;         // gate type 0..3 (16 rows each)
        const int s  = combo & 31;         // k-step
        char* wfhi = sm + SM_WF + (size_t)((0*4 + mt)*32 + s)*512;
        char* wflo = sm + SM_WF + (size_t)((1*4 + mt)*32 + s)*512;
        for (int l2 = q*8; l2 < q*8 + 8; ++l2) {
            const int r = l2 >> 2, c = 2*(l2 & 3);
            const float* w0 = W_hh + (size_t)(mt*512 + hu0 + r)*H_ + s*16 + c;
            const float* w1 = w0 + 8*H_;
            float2 w00 = *(const float2*)w0;
            float2 w02 = *(const float2*)(w0 + 8);
            float2 w10 = *(const float2*)w1;
            float2 w12 = *(const float2*)(w1 + 8);
            uint4 hi, lo;
            split2(w00, hi.x, lo.x);
            split2(w10, hi.y, lo.y);
            split2(w02, hi.z, lo.z);
            split2(w12, hi.w, lo.w);
            *(uint4*)(wfhi + l2*16) = hi;
            *(uint4*)(wflo + l2*16) = lo;
        }
    }

    // GEMM roles: warp = (mt in 0..3: gate type m16 tile, kh in 0..3: k quarter)
    const int mt = warp & 3;
    const int kh = warp >> 2;

    // Pointwise roles: b = tid>>4 (32 rows), u = tid&15 (1 unit) -> coalesced gmem
    const int pu = tid & 15;
    const int pb = tid >> 4;
    const int xl = x_len[b0 + pb];        // register-resident
    float creg = 0.f;
    float hreg = 0.f;                     // carried h (this thread owns this element)

    // Convert roles: thread = (cb batch row, jb4 k-phase, iq k-step quarter)
    const int cb  = tid >> 4;             // 0..31
    const int jb4 = tid & 3;              // 0..3
    const int iq  = (tid >> 2) & 3;       // 0..3
    const int cnt = cb >> 3;              // B n-tile
    const int cl2 = (cb & 7)*4 + jb4;     // fragment lane

    __syncthreads();

    for (int t = 0; t < T_; ++t) {
        const int cur = t & 1, nxt = cur ^ 1;

        // ---- Prefetch pointwise inputs (hidden under convert + GEMM) ----
        const int vb = __ldg(&x[(size_t)(b0 + pb)*T_ + t]);
        const float* pj = g_WihT + (size_t)vb*G_ + hu0 + pu;
        const float pji = __ldg(pj);
        const float pjf = __ldg(pj + 512);
        const float pjg = __ldg(pj + 1024);
        const float pjo = __ldg(pj + 1536);

        // ---- Convert h -> fp16 hi/lo B-fragment tiles ----
        // B k16n8 fragment: lane l holds b0 = rows 2*(l&3)+{0,1}, b1 = rows +8, col l>>2.
        {
            const float* hrow = g_h[cur] + (size_t)(b0 + cb)*H_;
            char* hfhi = sm + SM_HF + (size_t)(cnt*32)*256;
            char* hflo = hfhi + 4*32*256;
            #pragma unroll
            for (int i = iq*8; i < iq*8 + 8; ++i) {
                float2 v0 = *(const float2*)(hrow + 2*jb4 + 16*i);      // b0 halves
                float2 v1 = *(const float2*)(hrow + 2*jb4 + 16*i + 8);  // b1 halves
                uint2 hiw, low;
                split2(v0, hiw.x, low.x);
                split2(v1, hiw.y, low.y);
                const int off = i*256 + cl2*8;
                *(uint2*)(hfhi + off) = hiw;
                *(uint2*)(hflo + off) = low;
            }
        }
        __syncthreads();

        // ---- GEMM: fused 3-product fp16 split, single k sweep, reg-reused frags ----
        float d[4][4], d2[4][4];
        #pragma unroll
        for (int b = 0; b < 4; ++b)
            #pragma unroll
            for (int c = 0; c < 4; ++c) { d[b][c] = 0.f; d2[b][c] = 0.f; }

        {
            const char* Abh = sm + SM_WF + (size_t)mt*(32*512);
            const char* Abl = Abh + 4*(32*512);
            const char* Bbh = sm + SM_HF;
            const char* Bbl = Bbh + 4*(32*256);
            #pragma unroll 4
            for (int s8 = 0; s8 < 8; ++s8) {
                const int s = kh*8 + s8;
                uint4 Ahi = *(const uint4*)(Abh + s*512 + lane*16);
                uint4 Alo = *(const uint4*)(Abl + s*512 + lane*16);
                #pragma unroll
                for (int nt = 0; nt < 4; ++nt) {
                    uint2 Bhi = *(const uint2*)(Bbh + nt*(32*256) + s*256 + lane*8);
                    uint2 Blo = *(const uint2*)(Bbl + nt*(32*256) + s*256 + lane*8);
                    mma16816(d[nt],  Ahi, Bhi);   // hi*hi
                    mma16816(d2[nt], Ahi, Blo);   // hi*lo   (independent chain)
                    mma16816(d[nt],  Alo, Bhi);   // lo*hi
                }
            }
        }

        // ---- Stage k-split partials to Gs[kh] ----
        // D m16n8: lane holds d0=(r,c) d1=(r,c+1) d2=(r+8,c) d3=(r+8,c+1)
        {
            float* gsb = Gs + kh*2112;
            const int rr = lane >> 2, cc = 2*(lane & 3);
            const int g0 = mt*16 + rr;
            #pragma unroll
            for (int nt = 0; nt < 4; ++nt) {
                const int col = nt*8 + cc;
                gsb[g0*33 + col]         = d[nt][0] + d2[nt][0];
                gsb[g0*33 + col + 1]     = d[nt][1] + d2[nt][1];
                gsb[(g0+8)*33 + col]     = d[nt][2] + d2[nt][2];
                gsb[(g0+8)*33 + col + 1] = d[nt][3] + d2[nt][3];
            }
        }
        __syncthreads();

        // ---- Pointwise LSTM cell (1 h-unit per thread, c & h in registers) ----
        float outv;
        {
            const int b = pb, u = pu;
            float gv[4];
            #pragma unroll
            for (int gt = 0; gt < 4; ++gt) {
                const int g = gt*16 + u;
                gv[gt] = Gs[g*33 + b] + Gs[2112 + g*33 + b]
                       + Gs[2*2112 + g*33 + b] + Gs[3*2112 + g*33 + b];
            }
            const float iv  = sigf(gv[0] + pji);
            const float fv  = sigf(gv[1] + pjf);
            const float gvv = tanhf(gv[2] + pjg);
            const float ov  = sigf(gv[3] + pjo);
            const float cn  = fv*creg + iv*gvv;
            const float hn  = ov*tanhf(cn);

            const bool m = (t < xl);
            hreg = m ? hn : hreg;
            creg = m ? cn : creg;
            outv = m ? hn : 0.f;

            g_h[nxt][(size_t)(b0+b)*H_ + hu0 + u] = hreg;   // coalesced 64B runs
        }

        // ---- Grid barrier arrive (release g_h stores), overlap out[] with spin ----
        __syncthreads();
        if (t + 1 < T_) {
            if (tid == 0) {
                __threadfence();                 // publish block's g_h stores (gpu scope)
                atomicAdd(&g_bar, 1u);
            }
        }

        // sequence output — overlaps other CTAs' arrival / our spin
        out[((size_t)(b0+pb)*T_ + t)*H_ + hu0 + pu] = outv;
        if (t == T_ - 1) {
            const size_t hoff = (size_t)B_*T_*H_ + (size_t)(b0+pb)*H_ + hu0 + pu;
            out[hoff] = hreg;
            out[hoff + (size_t)B_*H_] = creg;
        }

        if (t + 1 < T_) {
            if (tid == 0) {
                const unsigned target = (unsigned)NBLK * (unsigned)(t + 1);
                while (*((volatile unsigned*)&g_bar) < target) { }
                __threadfence();                 // acquire
            }
            __syncthreads();
        }
    }
}

extern "C" void kernel_launch(void* const* d_in, const int* in_sizes, int n_in,
                              void* d_out, int out_size) {
    const int*   x     = (const int*)d_in[0];
    const int*   x_len = (const int*)d_in[1];
    const float* W_ih  = (const float*)d_in[2];
    const float* W_hh  = (const float*)d_in[3];
    const float* b_ih  = (const float*)d_in[4];
    const float* b_hh  = (const float*)d_in[5];
    float* out = (float*)d_out;

    cudaFuncSetAttribute(lstm_persistent,
                         cudaFuncAttributeMaxDynamicSharedMemorySize, SMEM_BYTES);

    init_kernel<<<256, 256>>>(W_ih, b_ih, b_hh);
    lstm_persistent<<<NBLK, NTHR, SMEM_BYTES>>>(x, x_len, W_hh, out);
}

// round 15
// speedup vs baseline: 1.6956x; 1.4518x over previous
#include <cuda_runtime.h>
#include <cuda_fp16.h>
#include <cstdint>

// Problem constants
#define B_   128
#define T_   1024
#define H_   512
#define G_   2048
#define V_   256
#define NBLK 128      // 32 gate-groups (16 units) x 4 batch-groups (32 rows)
#define NTHR 512      // 16 warps = 4 gate-type warps x 4 k-splits

// SMEM: only the gate staging buffer now
//  GS: 4 k-split partial gate buffers [64 g][33 b] f32 = 33792
#define SM_GS  0
#define SMEM_BYTES 33920

// Device-global scratch (allocation-free per harness rules)
__device__ float    g_WihT[V_*G_];        // projT[v][g] with biases folded
// h pre-split to fp16 hi/lo in B-fragment layout, double buffered:
// [buf][bg][hi/lo][(nt*32 + s)*32 + lane] (uint2 = 4 halves)
__device__ uint2    g_hsplit[2][4][2][4096];
__device__ unsigned g_bar;

__device__ __forceinline__ float sigf(float x) { return 1.0f / (1.0f + expf(-x)); }

__device__ __forceinline__ void mma16816(float d[4], const uint4& a, const uint2& b) {
    asm volatile(
        "mma.sync.aligned.m16n8k16.row.col.f32.f16.f16.f32 "
        "{%0,%1,%2,%3}, {%4,%5,%6,%7}, {%8,%9}, {%0,%1,%2,%3};"
        : "+f"(d[0]), "+f"(d[1]), "+f"(d[2]), "+f"(d[3])
        : "r"(a.x), "r"(a.y), "r"(a.z), "r"(a.w), "r"(b.x), "r"(b.y));
}

__device__ __forceinline__ uint32_t h2u(__half2 h) { return *(uint32_t*)&h; }

// fp32 pair -> (hi fp16x2, lo fp16x2) with lo = x - float(hi)
__device__ __forceinline__ void split2(float2 v, uint32_t& hi, uint32_t& lo) {
    __half2 h = __floats2half2_rn(v.x, v.y);
    float2 f = __half22float2(h);
    __half2 l = __floats2half2_rn(v.x - f.x, v.y - f.y);
    hi = h2u(h); lo = h2u(l);
}

// Per-launch init: reset barrier, zero h-split buffers, build projection table
// projT[v][g] = W_ih[g][v] + b_ih[g] + b_hh[g]
__global__ void init_kernel(const float* __restrict__ W_ih,
                            const float* __restrict__ b_ih,
                            const float* __restrict__ b_hh) {
    int idx = blockIdx.x * blockDim.x + threadIdx.x;
    int stride = gridDim.x * blockDim.x;
    if (idx == 0) g_bar = 0u;
    for (int i = idx; i < V_*G_; i += stride) {
        int v = i >> 11;
        int g = i & (G_ - 1);
        g_WihT[i] = W_ih[g*V_ + v] + b_ih[g] + b_hh[g];
    }
    uint2* hs = &g_hsplit[0][0][0][0];
    for (int i = idx; i < 2*4*2*4096; i += stride) hs[i] = make_uint2(0u, 0u);
}

extern __shared__ char smem_raw[];

__global__ __launch_bounds__(NTHR, 1)
void lstm_persistent(const int* __restrict__ x, const int* __restrict__ x_len,
                     const float* __restrict__ W_hh, float* __restrict__ out) {
    float* Gs = (float*)(smem_raw + SM_GS);

    const int tid  = threadIdx.x;
    const int lane = tid & 31;
    const int warp = tid >> 5;
    const int gg   = blockIdx.x & 31;   // gate group (16 h-units, 64 gate rows)
    const int bg   = blockIdx.x >> 5;   // batch group (32 rows)
    const int hu0  = gg * 16;
    const int b0   = bg * 32;

    // GEMM roles: warp = (mt in 0..3: gate type m16 tile, kh in 0..3: k quarter)
    const int mt = warp & 3;
    const int kh = warp >> 2;

    // ---- Prologue: load this warp's A fragments (hi/lo fp16) into REGISTERS ----
    // A m16n8k16 fragment: lane l holds a0=(r,c..c+1) a1=(r+8,c..) a2=(r,c+8..) a3=(r+8,c+8..)
    // with r=l>>2, c=2*(l&3). Weight-stationary for all 1024 steps.
    uint4 Ahi[8], Alo[8];
    {
        const int r = lane >> 2, c = 2*(lane & 3);
        #pragma unroll
        for (int s8 = 0; s8 < 8; ++s8) {
            const int s = kh*8 + s8;
            const float* w0 = W_hh + (size_t)(mt*512 + hu0 + r)*H_ + s*16 + c;
            const float* w1 = w0 + 8*H_;
            float2 w00 = *(const float2*)w0;
            float2 w02 = *(const float2*)(w0 + 8);
            float2 w10 = *(const float2*)w1;
            float2 w12 = *(const float2*)(w1 + 8);
            split2(w00, Ahi[s8].x, Alo[s8].x);
            split2(w10, Ahi[s8].y, Alo[s8].y);
            split2(w02, Ahi[s8].z, Alo[s8].z);
            split2(w12, Ahi[s8].w, Alo[s8].w);
        }
    }

    // Pointwise roles: b = tid>>4 (32 rows), u = tid&15 (1 unit) -> coalesced gmem
    const int pu = tid & 15;
    const int pb = tid >> 4;
    const int xl = x_len[b0 + pb];        // register-resident
    float creg = 0.f;
    float hreg = 0.f;                     // carried h (this thread owns this element)

    // h-split writer mapping: this thread's h element (b=pb, k=hu0+pu) lands at
    // fragment (nt = pb>>3, s = gg), lane (pb&7)*4 + ((pu>>1)&3),
    // half index within uint2 = (pu>>3)*2 + (pu&1)
    const int hw_idx4 = (((pb >> 3)*32 + gg)*32 + ((pb & 7)*4 + ((pu >> 1) & 3)))*4
                      + ((pu >> 3)*2) + (pu & 1);

    __syncthreads();

    for (int t = 0; t < T_; ++t) {
        const int cur = t & 1, nxt = cur ^ 1;

        // ---- Prefetch pointwise inputs (hidden under GEMM) ----
        const int vb = __ldg(&x[(size_t)(b0 + pb)*T_ + t]);
        const float* pj = g_WihT + (size_t)vb*G_ + hu0 + pu;
        const float pji = __ldg(pj);
        const float pjf = __ldg(pj + 512);
        const float pjg = __ldg(pj + 1024);
        const float pjo = __ldg(pj + 1536);

        // ---- GEMM: fused 3-product fp16 split, A from registers, B from global ----
        float d[4][4];
        #pragma unroll
        for (int b = 0; b < 4; ++b)
            #pragma unroll
            for (int c = 0; c < 4; ++c) d[b][c] = 0.f;

        {
            const uint2* Bh = g_hsplit[cur][bg][0];
            const uint2* Bl = g_hsplit[cur][bg][1];
            #pragma unroll
            for (int s8 = 0; s8 < 8; ++s8) {
                const int s = kh*8 + s8;
                #pragma unroll
                for (int nt = 0; nt < 4; ++nt) {
                    const uint2 Bhi = Bh[(nt*32 + s)*32 + lane];
                    const uint2 Blo = Bl[(nt*32 + s)*32 + lane];
                    mma16816(d[nt], Ahi[s8], Bhi);   // hi*hi
                    mma16816(d[nt], Ahi[s8], Blo);   // hi*lo
                    mma16816(d[nt], Alo[s8], Bhi);   // lo*hi
                }
            }
        }

        // ---- Stage k-split partials to Gs[kh] ----
        // D m16n8: lane holds d0=(r,c) d1=(r,c+1) d2=(r+8,c) d3=(r+8,c+1)
        {
            float* gsb = Gs + kh*2112;
            const int rr = lane >> 2, cc = 2*(lane & 3);
            const int g0 = mt*16 + rr;
            #pragma unroll
            for (int nt = 0; nt < 4; ++nt) {
                const int col = nt*8 + cc;
                gsb[g0*33 + col]         = d[nt][0];
                gsb[g0*33 + col + 1]     = d[nt][1];
                gsb[(g0+8)*33 + col]     = d[nt][2];
                gsb[(g0+8)*33 + col + 1] = d[nt][3];
            }
        }
        __syncthreads();

        // ---- Pointwise LSTM cell (1 h-unit per thread, c & h in registers) ----
        float outv;
        {
            const int b = pb, u = pu;
            float gv[4];
            #pragma unroll
            for (int gt = 0; gt < 4; ++gt) {
                const int g = gt*16 + u;
                gv[gt] = Gs[g*33 + b] + Gs[2112 + g*33 + b]
                       + Gs[2*2112 + g*33 + b] + Gs[3*2112 + g*33 + b];
            }
            const float iv  = sigf(gv[0] + pji);
            const float fv  = sigf(gv[1] + pjf);
            const float gvv = tanhf(gv[2] + pjg);
            const float ov  = sigf(gv[3] + pjo);
            const float cn  = fv*creg + iv*gvv;
            const float hn  = ov*tanhf(cn);

            const bool m = (t < xl);
            hreg = m ? hn : hreg;
            creg = m ? cn : creg;
            outv = m ? hn : 0.f;

            // split h -> fp16 hi/lo, store directly into next-step B-fragment layout
            const __half hi_h = __float2half_rn(hreg);
            const __half lo_h = __float2half_rn(hreg - __half2float(hi_h));
            ((__half*)g_hsplit[nxt][bg][0])[hw_idx4] = hi_h;
            ((__half*)g_hsplit[nxt][bg][1])[hw_idx4] = lo_h;
        }

        // ---- Grid barrier arrive (release h stores), overlap out[] with spin ----
        __syncthreads();
        if (t + 1 < T_) {
            if (tid == 0) {
                __threadfence();                 // publish block's h-split stores
                atomicAdd(&g_bar, 1u);
            }
        }

        // sequence output — overlaps other CTAs' arrival / our spin
        out[((size_t)(b0+pb)*T_ + t)*H_ + hu0 + pu] = outv;
        if (t == T_ - 1) {
            const size_t hoff = (size_t)B_*T_*H_ + (size_t)(b0+pb)*H_ + hu0 + pu;
            out[hoff] = hreg;
            out[hoff + (size_t)B_*H_] = creg;
        }

        if (t + 1 < T_) {
            if (tid == 0) {
                const unsigned target = (unsigned)NBLK * (unsigned)(t + 1);
                while (*((volatile unsigned*)&g_bar) < target) { }
                __threadfence();                 // acquire (+ L1 invalidate)
            }
            __syncthreads();
        }
    }
}

extern "C" void kernel_launch(void* const* d_in, const int* in_sizes, int n_in,
                              void* d_out, int out_size) {
    const int*   x     = (const int*)d_in[0];
    const int*   x_len = (const int*)d_in[1];
    const float* W_ih  = (const float*)d_in[2];
    const float* W_hh  = (const float*)d_in[3];
    const float* b_ih  = (const float*)d_in[4];
    const float* b_hh  = (const float*)d_in[5];
    float* out = (float*)d_out;

    cudaFuncSetAttribute(lstm_persistent,
                         cudaFuncAttributeMaxDynamicSharedMemorySize, SMEM_BYTES);

    init_kernel<<<256, 256>>>(W_ih, b_ih, b_hh);
    lstm_persistent<<<NBLK, NTHR, SMEM_BYTES>>>(x, x_len, W_hh, out);
}